// round 4
// baseline (speedup 1.0000x reference)
#include <cuda_runtime.h>
#include <math.h>

// Problem constants
#define B 4
#define C 64
#define IC 16
#define H 128
#define W 128
#define DH 64
#define DW 64
#define N 4096          // DH*DW
#define BN_COUNT (B*H*W) // 65536 elems per channel

// ------------------------- scratch (static device) -------------------------
__device__ float g_qkv[3 * B * N * IC];        // [which][b*N+n][16]  which: 0=Q(theta) 1=K(phi) 2=V(g)
__device__ float g_opart[2 * B * N * IC];      // split-K partial O
__device__ float g_lpart[2 * B * N];           // split-K partial l
__device__ float g_y[B * N * IC];              // merged attention output  [b*N+n][16]
__device__ float g_z[B * C * H * W];           // residual sum, pre-BN
__device__ float g_bnpart[B * H * C * 2];      // per-(b,h) row partial sum/sumsq per channel
__device__ float g_bnstat[C * 2];              // mean, rstd

// ------------------- K1: downsample (point-sample odd pixels) + QKV projections -------------------
// jax scale_and_translate, scale=0.5, trans=-0.25  =>  sample_f = 2*o + 1 (exact hit)
__global__ void k_down_proj(const float* __restrict__ x,
                            const float* __restrict__ gw,  const float* __restrict__ gb,
                            const float* __restrict__ thw, const float* __restrict__ thb,
                            const float* __restrict__ phw, const float* __restrict__ phb)
{
    __shared__ float xd[64][64];    // [c][p]
    __shared__ float Wm[48][64];    // rows 0..15 theta, 16..31 phi, 32..47 g
    __shared__ float Bm[48];

    int b  = blockIdx.x >> 6;
    int oi = blockIdx.x & 63;
    int t  = threadIdx.x;  // 256

    for (int idx = t; idx < 16 * 64; idx += 256) {
        Wm[idx >> 6][idx & 63]        = thw[idx];
        Wm[16 + (idx >> 6)][idx & 63] = phw[idx];
        Wm[32 + (idx >> 6)][idx & 63] = gw[idx];
    }
    if (t < 16) { Bm[t] = thb[t]; Bm[16 + t] = phb[t]; Bm[32 + t] = gb[t]; }

    // downsample: xd[c][oj] = x[2*oi+1][2*oj+1]  (pure subsample)
    for (int idx = t; idx < 4096; idx += 256) {
        int c = idx >> 6, oj = idx & 63;
        xd[c][oj] = x[(((size_t)b * C + c) * H + 2 * oi + 1) * W + 2 * oj + 1];
    }
    __syncthreads();

    int base_n = b * N + oi * 64;
    for (int idx = t; idx < 3072; idx += 256) {
        int p = idx & 63, o = idx >> 6;   // o in 0..47
        float s0 = 0.f, s1 = 0.f, s2 = 0.f, s3 = 0.f;
        #pragma unroll
        for (int c = 0; c < 64; c += 4) {
            s0 += Wm[o][c]     * xd[c][p];
            s1 += Wm[o][c + 1] * xd[c + 1][p];
            s2 += Wm[o][c + 2] * xd[c + 2][p];
            s3 += Wm[o][c + 3] * xd[c + 3][p];
        }
        float s = Bm[o] + ((s0 + s1) + (s2 + s3));
        int which = o >> 4, oo = o & 15;
        g_qkv[((size_t)which * (B * N) + (base_n + p)) * IC + oo] = s;
    }
}

// ------------------- K2: flash attention (no-max online softmax, split-K=2) -------------------
#define TK 128
__global__ void __launch_bounds__(128, 8) k_attn()
{
    __shared__ float4 Ks[TK * 4];
    __shared__ float4 Vs[TK * 4];

    int cta  = blockIdx.x;          // 0..255
    int b    = cta >> 6;
    int qt   = (cta & 63) >> 1;     // 0..31 query tile
    int half = cta & 1;             // split-K half
    int t    = threadIdx.x;         // 128

    int n = b * N + qt * 128 + t;   // this thread's query

    const float* Q = g_qkv;
    const float* K = g_qkv + (size_t)(B * N) * IC;
    const float* V = g_qkv + (size_t)2 * (B * N) * IC;

    const float4* qv = (const float4*)(Q + (size_t)n * IC);
    float4 q0 = qv[0], q1 = qv[1], q2 = qv[2], q3 = qv[3];

    float4 o0 = {0,0,0,0}, o1 = {0,0,0,0}, o2 = {0,0,0,0}, o3 = {0,0,0,0};
    float l = 0.f;

    int kbase = b * N + half * 2048;
    for (int tile = 0; tile < 2048; tile += TK) {
        const float4* Kg = (const float4*)(K + (size_t)(kbase + tile) * IC);
        const float4* Vg = (const float4*)(V + (size_t)(kbase + tile) * IC);
        #pragma unroll
        for (int i = t; i < TK * 4; i += 128) { Ks[i] = Kg[i]; Vs[i] = Vg[i]; }
        __syncthreads();

        #pragma unroll 4
        for (int kk = 0; kk < TK; kk++) {
            float4 ka = Ks[kk * 4 + 0], kb = Ks[kk * 4 + 1];
            float4 kc = Ks[kk * 4 + 2], kd = Ks[kk * 4 + 3];
            float s0 = q0.x * ka.x + q0.y * ka.y + q0.z * ka.z + q0.w * ka.w;
            float s1 = q1.x * kb.x + q1.y * kb.y + q1.z * kb.z + q1.w * kb.w;
            float s2 = q2.x * kc.x + q2.y * kc.y + q2.z * kc.z + q2.w * kc.w;
            float s3 = q3.x * kd.x + q3.y * kd.y + q3.z * kd.z + q3.w * kd.w;
            float p  = __expf((s0 + s1) + (s2 + s3));
            l += p;
            float4 va = Vs[kk * 4 + 0], vb = Vs[kk * 4 + 1];
            float4 vc = Vs[kk * 4 + 2], vd = Vs[kk * 4 + 3];
            o0.x += p * va.x; o0.y += p * va.y; o0.z += p * va.z; o0.w += p * va.w;
            o1.x += p * vb.x; o1.y += p * vb.y; o1.z += p * vb.z; o1.w += p * vb.w;
            o2.x += p * vc.x; o2.y += p * vc.y; o2.z += p * vc.z; o2.w += p * vc.w;
            o3.x += p * vd.x; o3.y += p * vd.y; o3.z += p * vd.z; o3.w += p * vd.w;
        }
        __syncthreads();
    }

    float4* O = (float4*)(g_opart + ((size_t)half * (B * N) + n) * IC);
    O[0] = o0; O[1] = o1; O[2] = o2; O[3] = o3;
    g_lpart[(size_t)half * (B * N) + n] = l;
}

// ------------------- K2b: merge split-K partials -------------------
__global__ void k_merge()
{
    int n = blockIdx.x * 256 + threadIdx.x;   // 0..16383
    if (n >= B * N) return;
    float l   = g_lpart[n] + g_lpart[B * N + n];
    float inv = 1.f / l;
    const float4* a = (const float4*)(g_opart + (size_t)n * IC);
    const float4* b = (const float4*)(g_opart + ((size_t)(B * N) + n) * IC);
    float4* y = (float4*)(g_y + (size_t)n * IC);
    #pragma unroll
    for (int i = 0; i < 4; i++) {
        float4 av = a[i], bv = b[i], r;
        r.x = (av.x + bv.x) * inv; r.y = (av.y + bv.y) * inv;
        r.z = (av.z + bv.z) * inv; r.w = (av.w + bv.w) * inv;
        y[i] = r;
    }
}

// ------------------- K3: upsample + out conv + residual + BN partials -------------------
// jax scale_and_translate, scale=2, trans=+0.5  =>  sample_f = 0.5*o - 0.5
// (boundary o=0 renormalizes to weight 1.0 on index 0 == clamp-both-taps)
__global__ void k_out(const float* __restrict__ x,
                      const float* __restrict__ ow, const float* __restrict__ ob)
{
    __shared__ float yr[16][64];      // vertically interpolated row
    __shared__ float yup[16][128];    // fully interpolated row
    __shared__ float Wo[64][16];
    __shared__ float wsum[8][64];
    __shared__ float wssq[8][64];

    int b = blockIdx.x >> 7;
    int h = blockIdx.x & 127;
    int t = threadIdx.x;  // 256

    for (int idx = t; idx < 1024; idx += 256) Wo[idx >> 4][idx & 15] = ow[idx];

    // vertical: input coord = h/2 - 0.5 (clamped)
    float fh = 0.5f * (float)h - 0.5f;
    int   ihf = (int)floorf(fh);
    float w1  = fh - (float)ihf;
    int ih0 = ihf < 0 ? 0 : ihf;
    int ih1 = (ihf + 1) > 63 ? 63 : (ihf + 1);

    for (int idx = t; idx < 1024; idx += 256) {
        int i = idx >> 6, jw = idx & 63;
        float a = g_y[((size_t)b * N + ih0 * 64 + jw) * IC + i];
        float c = g_y[((size_t)b * N + ih1 * 64 + jw) * IC + i];
        yr[i][jw] = (1.f - w1) * a + w1 * c;
    }
    for (int idx = t; idx < 512; idx += 256) {
        wsum[idx >> 6][idx & 63] = 0.f;
        wssq[idx >> 6][idx & 63] = 0.f;
    }
    __syncthreads();

    for (int idx = t; idx < 2048; idx += 256) {
        int i = idx >> 7, w = idx & 127;
        float fw = 0.5f * (float)w - 0.5f;
        int   jf = (int)floorf(fw);
        float ww = fw - (float)jf;
        int j0 = jf < 0 ? 0 : jf;
        int j1 = (jf + 1) > 63 ? 63 : (jf + 1);
        yup[i][w] = (1.f - ww) * yr[i][j0] + ww * yr[i][j1];
    }
    __syncthreads();

    int c2   = t >> 7;        // 0: even channels (warps 0-3), 1: odd (warps 4-7)
    int w    = t & 127;
    int warp = t >> 5;
    int lane = t & 31;

    const float* xrow = x   + ((size_t)b * C * H + h) * W;
    float*       zrow = g_z + ((size_t)b * C * H + h) * W;

    for (int c = c2; c < C; c += 2) {
        float s = ob[c];
        #pragma unroll
        for (int i = 0; i < 16; i++) s += Wo[c][i] * yup[i][w];
        float z = xrow[(size_t)c * (H * W) + w] + s;
        zrow[(size_t)c * (H * W) + w] = z;

        float vs = z, vq = z * z;
        #pragma unroll
        for (int off = 16; off; off >>= 1) {
            vs += __shfl_down_sync(0xffffffffu, vs, off);
            vq += __shfl_down_sync(0xffffffffu, vq, off);
        }
        if (lane == 0) { wsum[warp][c] += vs; wssq[warp][c] += vq; }
    }
    __syncthreads();

    if (t < 64) {
        int c = t;
        int base = (c & 1) ? 4 : 0;
        float s = ((wsum[base][c] + wsum[base + 1][c]) + (wsum[base + 2][c] + wsum[base + 3][c]));
        float q = ((wssq[base][c] + wssq[base + 1][c]) + (wssq[base + 2][c] + wssq[base + 3][c]));
        int row = b * H + h;
        g_bnpart[((size_t)row * C + c) * 2 + 0] = s;
        g_bnpart[((size_t)row * C + c) * 2 + 1] = q;
    }
}

// ------------------- K4: finalize BN stats (deterministic fixed-order sums) -------------------
__global__ void k_stats()
{
    __shared__ float ss[256], sq[256];
    int t = threadIdx.x;           // 256
    int c = t & 63, qtr = t >> 6;  // 4 threads per channel, 128 rows each
    float s = 0.f, q = 0.f;
    int r0 = qtr * 128;
    #pragma unroll 8
    for (int r = r0; r < r0 + 128; r++) {
        s += g_bnpart[((size_t)r * C + c) * 2 + 0];
        q += g_bnpart[((size_t)r * C + c) * 2 + 1];
    }
    ss[t] = s; sq[t] = q;
    __syncthreads();
    if (qtr == 0) {
        float S = ((ss[c] + ss[64 + c]) + (ss[128 + c] + ss[192 + c]));
        float Q = ((sq[c] + sq[64 + c]) + (sq[128 + c] + sq[192 + c]));
        float mean = S * (1.f / (float)BN_COUNT);
        float var  = Q * (1.f / (float)BN_COUNT) - mean * mean;
        g_bnstat[c * 2 + 0] = mean;
        g_bnstat[c * 2 + 1] = rsqrtf(var + 1e-5f);
    }
}

// ------------------- K5: normalize -------------------
__global__ void k_norm(const float* __restrict__ gamma, const float* __restrict__ beta,
                       float* __restrict__ out)
{
    size_t i4 = (size_t)blockIdx.x * 256 + threadIdx.x;  // float4 index, total 1048576
    int c = (int)((i4 >> 12) & 63);
    float mean = g_bnstat[c * 2 + 0];
    float rstd = g_bnstat[c * 2 + 1];
    float ga = gamma[c] * rstd;
    float be = beta[c] - mean * ga;
    float4 z = ((const float4*)g_z)[i4];
    float4 r;
    r.x = z.x * ga + be; r.y = z.y * ga + be;
    r.z = z.z * ga + be; r.w = z.w * ga + be;
    ((float4*)out)[i4] = r;
}

// ------------------------------- launch -------------------------------
extern "C" void kernel_launch(void* const* d_in, const int* in_sizes, int n_in,
                              void* d_out, int out_size)
{
    const float* x     = (const float*)d_in[0];
    const float* g_w   = (const float*)d_in[1];
    const float* g_b   = (const float*)d_in[2];
    const float* th_w  = (const float*)d_in[3];
    const float* th_b  = (const float*)d_in[4];
    const float* ph_w  = (const float*)d_in[5];
    const float* ph_b  = (const float*)d_in[6];
    const float* out_w = (const float*)d_in[7];
    const float* out_b = (const float*)d_in[8];
    const float* gamma = (const float*)d_in[9];
    const float* beta  = (const float*)d_in[10];
    float* out = (float*)d_out;

    k_down_proj<<<B * 64, 256>>>(x, g_w, g_b, th_w, th_b, ph_w, ph_b);
    k_attn<<<256, 128>>>();
    k_merge<<<64, 256>>>();
    k_out<<<B * H, 256>>>(x, out_w, out_b);
    k_stats<<<1, 256>>>();
    k_norm<<<4096, 256>>>(gamma, beta, out);
}

// round 5
// speedup vs baseline: 1.1174x; 1.1174x over previous
#include <cuda_runtime.h>
#include <math.h>

// Problem constants
#define B 4
#define C 64
#define IC 16
#define H 128
#define W 128
#define DH 64
#define DW 64
#define N 4096          // DH*DW
#define BN_COUNT (B*H*W) // 65536 elems per channel
#define SPLITK 4

typedef unsigned long long u64;

// packed f32x2 helpers (sm_100+): 2 fp32 MACs per fma-pipe issue (SASS FFMA2)
__device__ __forceinline__ u64 fma2(u64 a, u64 b, u64 c) {
    u64 d; asm("fma.rn.f32x2 %0,%1,%2,%3;" : "=l"(d) : "l"(a), "l"(b), "l"(c)); return d;
}
__device__ __forceinline__ u64 mul2(u64 a, u64 b) {
    u64 d; asm("mul.rn.f32x2 %0,%1,%2;" : "=l"(d) : "l"(a), "l"(b)); return d;
}
__device__ __forceinline__ u64 add2(u64 a, u64 b) {
    u64 d; asm("add.rn.f32x2 %0,%1,%2;" : "=l"(d) : "l"(a), "l"(b)); return d;
}

// ------------------------- scratch (static device) -------------------------
__device__ float g_qkv[3 * B * N * IC];            // [which][b*N+n][16]  0=Q 1=K 2=V
__device__ float g_opart[SPLITK * B * N * IC];     // split-K partial O
__device__ float g_lpart[SPLITK * B * N];          // split-K partial l
__device__ float g_y[B * N * IC];                  // merged attention output
__device__ float g_z[B * C * H * W];               // residual sum, pre-BN
__device__ float g_bnpart[B * H * C * 2];          // per-(b,h) partial sum/sumsq per channel
__device__ float g_bnstat[C * 2];                  // mean, rstd

// ------------------- K1: downsample (point-sample odd pixels) + QKV projections -------------------
// jax scale_and_translate, scale=0.5, trans=-0.25  =>  sample_f = 2*o + 1 (exact hit)
__global__ void k_down_proj(const float* __restrict__ x,
                            const float* __restrict__ gw,  const float* __restrict__ gb,
                            const float* __restrict__ thw, const float* __restrict__ thb,
                            const float* __restrict__ phw, const float* __restrict__ phb)
{
    __shared__ float xd[64][64];    // [c][p]
    __shared__ float Wm[48][64];    // rows 0..15 theta, 16..31 phi, 32..47 g
    __shared__ float Bm[48];

    int b  = blockIdx.x >> 6;
    int oi = blockIdx.x & 63;
    int t  = threadIdx.x;  // 256

    for (int idx = t; idx < 16 * 64; idx += 256) {
        Wm[idx >> 6][idx & 63]        = thw[idx];
        Wm[16 + (idx >> 6)][idx & 63] = phw[idx];
        Wm[32 + (idx >> 6)][idx & 63] = gw[idx];
    }
    if (t < 16) { Bm[t] = thb[t]; Bm[16 + t] = phb[t]; Bm[32 + t] = gb[t]; }

    for (int idx = t; idx < 4096; idx += 256) {
        int c = idx >> 6, oj = idx & 63;
        xd[c][oj] = x[(((size_t)b * C + c) * H + 2 * oi + 1) * W + 2 * oj + 1];
    }
    __syncthreads();

    int base_n = b * N + oi * 64;
    for (int idx = t; idx < 3072; idx += 256) {
        int p = idx & 63, o = idx >> 6;   // o in 0..47
        float s0 = 0.f, s1 = 0.f, s2 = 0.f, s3 = 0.f;
        #pragma unroll
        for (int c = 0; c < 64; c += 4) {
            s0 += Wm[o][c]     * xd[c][p];
            s1 += Wm[o][c + 1] * xd[c + 1][p];
            s2 += Wm[o][c + 2] * xd[c + 2][p];
            s3 += Wm[o][c + 3] * xd[c + 3][p];
        }
        float s = Bm[o] + ((s0 + s1) + (s2 + s3));
        int which = o >> 4, oo = o & 15;
        g_qkv[((size_t)which * (B * N) + (base_n + p)) * IC + oo] = s;
    }
}

// ------------------- K2: flash attention (no-max online softmax, split-K=4, packed f32x2) -------------------
#define TK 128
#define KPC (N / SPLITK)   // keys per CTA = 1024
__global__ void __launch_bounds__(128, 8) k_attn()
{
    __shared__ ulonglong2 Ks[TK * 4];   // row j at [j*4..j*4+3], each 16B = 2 packed pairs
    __shared__ ulonglong2 Vs[TK * 4];

    int cta  = blockIdx.x;              // 0..511
    int b    = cta >> 7;
    int rest = cta & 127;
    int qt   = rest >> 2;               // 0..31 query tile
    int part = rest & 3;                // split-K quarter
    int t    = threadIdx.x;             // 128

    int n = b * N + qt * 128 + t;       // this thread's query

    const float* Q = g_qkv;
    const float* K = g_qkv + (size_t)(B * N) * IC;
    const float* V = g_qkv + (size_t)2 * (B * N) * IC;

    u64 q[8];
    {
        const u64* qv = (const u64*)(Q + (size_t)n * IC);
        #pragma unroll
        for (int i = 0; i < 8; i++) q[i] = qv[i];
    }

    u64 o[8];
    #pragma unroll
    for (int i = 0; i < 8; i++) o[i] = 0ull;
    float l = 0.f;

    int kbase = b * N + part * KPC;
    for (int tile = 0; tile < KPC; tile += TK) {
        const ulonglong2* Kg = (const ulonglong2*)(K + (size_t)(kbase + tile) * IC);
        const ulonglong2* Vg = (const ulonglong2*)(V + (size_t)(kbase + tile) * IC);
        #pragma unroll
        for (int i = t; i < TK * 4; i += 128) { Ks[i] = Kg[i]; Vs[i] = Vg[i]; }
        __syncthreads();

        #pragma unroll 4
        for (int kk = 0; kk < TK; kk++) {
            ulonglong2 ka = Ks[kk * 4 + 0], kb = Ks[kk * 4 + 1];
            ulonglong2 kc = Ks[kk * 4 + 2], kd = Ks[kk * 4 + 3];
            // two independent packed dot chains (depth 4)
            u64 sA = mul2(q[0], ka.x);
            u64 sB = mul2(q[1], ka.y);
            sA = fma2(q[2], kb.x, sA);
            sB = fma2(q[3], kb.y, sB);
            sA = fma2(q[4], kc.x, sA);
            sB = fma2(q[5], kc.y, sB);
            sA = fma2(q[6], kd.x, sA);
            sB = fma2(q[7], kd.y, sB);
            u64 sP = add2(sA, sB);
            float lo, hi;
            asm("mov.b64 {%0,%1},%2;" : "=f"(lo), "=f"(hi) : "l"(sP));
            float p = __expf(lo + hi);
            l += p;
            u64 p2;
            asm("mov.b64 %0,{%1,%1};" : "=l"(p2) : "f"(p));
            ulonglong2 va = Vs[kk * 4 + 0], vb = Vs[kk * 4 + 1];
            ulonglong2 vc = Vs[kk * 4 + 2], vd = Vs[kk * 4 + 3];
            o[0] = fma2(p2, va.x, o[0]);
            o[1] = fma2(p2, va.y, o[1]);
            o[2] = fma2(p2, vb.x, o[2]);
            o[3] = fma2(p2, vb.y, o[3]);
            o[4] = fma2(p2, vc.x, o[4]);
            o[5] = fma2(p2, vc.y, o[5]);
            o[6] = fma2(p2, vd.x, o[6]);
            o[7] = fma2(p2, vd.y, o[7]);
        }
        __syncthreads();
    }

    ulonglong2* O = (ulonglong2*)(g_opart + ((size_t)part * (B * N) + n) * IC);
    O[0] = make_ulonglong2(o[0], o[1]);
    O[1] = make_ulonglong2(o[2], o[3]);
    O[2] = make_ulonglong2(o[4], o[5]);
    O[3] = make_ulonglong2(o[6], o[7]);
    g_lpart[(size_t)part * (B * N) + n] = l;
}

// ------------------- K2b: merge split-K partials -------------------
__global__ void k_merge()
{
    int n = blockIdx.x * 256 + threadIdx.x;   // 0..16383
    if (n >= B * N) return;
    float l = 0.f;
    #pragma unroll
    for (int p = 0; p < SPLITK; p++) l += g_lpart[(size_t)p * (B * N) + n];
    float inv = 1.f / l;
    float acc[16];
    #pragma unroll
    for (int i = 0; i < 16; i++) acc[i] = 0.f;
    #pragma unroll
    for (int p = 0; p < SPLITK; p++) {
        const float4* a = (const float4*)(g_opart + ((size_t)p * (B * N) + n) * IC);
        #pragma unroll
        for (int i = 0; i < 4; i++) {
            float4 v = a[i];
            acc[i * 4 + 0] += v.x; acc[i * 4 + 1] += v.y;
            acc[i * 4 + 2] += v.z; acc[i * 4 + 3] += v.w;
        }
    }
    float4* y = (float4*)(g_y + (size_t)n * IC);
    #pragma unroll
    for (int i = 0; i < 4; i++) {
        float4 r;
        r.x = acc[i * 4 + 0] * inv; r.y = acc[i * 4 + 1] * inv;
        r.z = acc[i * 4 + 2] * inv; r.w = acc[i * 4 + 3] * inv;
        y[i] = r;
    }
}

// ------------------- K3: upsample + out conv + residual + BN partials -------------------
// jax scale_and_translate, scale=2, trans=+0.5  =>  sample_f = 0.5*o - 0.5 (clamped taps)
__global__ void k_out(const float* __restrict__ x,
                      const float* __restrict__ ow, const float* __restrict__ ob)
{
    __shared__ float yr[16][64];      // vertically interpolated row
    __shared__ float yup[16][128];    // fully interpolated row
    __shared__ float Wo[64][16];
    __shared__ float wsum[8][64];
    __shared__ float wssq[8][64];

    int b = blockIdx.x >> 7;
    int h = blockIdx.x & 127;
    int t = threadIdx.x;  // 256

    for (int idx = t; idx < 1024; idx += 256) Wo[idx >> 4][idx & 15] = ow[idx];

    float fh = 0.5f * (float)h - 0.5f;
    int   ihf = (int)floorf(fh);
    float w1  = fh - (float)ihf;
    int ih0 = ihf < 0 ? 0 : ihf;
    int ih1 = (ihf + 1) > 63 ? 63 : (ihf + 1);

    for (int idx = t; idx < 1024; idx += 256) {
        int i = idx >> 6, jw = idx & 63;
        float a = g_y[((size_t)b * N + ih0 * 64 + jw) * IC + i];
        float c = g_y[((size_t)b * N + ih1 * 64 + jw) * IC + i];
        yr[i][jw] = (1.f - w1) * a + w1 * c;
    }
    for (int idx = t; idx < 512; idx += 256) {
        wsum[idx >> 6][idx & 63] = 0.f;
        wssq[idx >> 6][idx & 63] = 0.f;
    }
    __syncthreads();

    for (int idx = t; idx < 2048; idx += 256) {
        int i = idx >> 7, w = idx & 127;
        float fw = 0.5f * (float)w - 0.5f;
        int   jf = (int)floorf(fw);
        float ww = fw - (float)jf;
        int j0 = jf < 0 ? 0 : jf;
        int j1 = (jf + 1) > 63 ? 63 : (jf + 1);
        yup[i][w] = (1.f - ww) * yr[i][j0] + ww * yr[i][j1];
    }
    __syncthreads();

    int c2   = t >> 7;
    int w    = t & 127;
    int warp = t >> 5;
    int lane = t & 31;

    const float* xrow = x   + ((size_t)b * C * H + h) * W;
    float*       zrow = g_z + ((size_t)b * C * H + h) * W;

    for (int c = c2; c < C; c += 2) {
        float s = ob[c];
        #pragma unroll
        for (int i = 0; i < 16; i++) s += Wo[c][i] * yup[i][w];
        float z = xrow[(size_t)c * (H * W) + w] + s;
        zrow[(size_t)c * (H * W) + w] = z;

        float vs = z, vq = z * z;
        #pragma unroll
        for (int off = 16; off; off >>= 1) {
            vs += __shfl_down_sync(0xffffffffu, vs, off);
            vq += __shfl_down_sync(0xffffffffu, vq, off);
        }
        if (lane == 0) { wsum[warp][c] += vs; wssq[warp][c] += vq; }
    }
    __syncthreads();

    if (t < 64) {
        int c = t;
        int base = (c & 1) ? 4 : 0;
        float s = ((wsum[base][c] + wsum[base + 1][c]) + (wsum[base + 2][c] + wsum[base + 3][c]));
        float q = ((wssq[base][c] + wssq[base + 1][c]) + (wssq[base + 2][c] + wssq[base + 3][c]));
        int row = b * H + h;
        g_bnpart[((size_t)row * C + c) * 2 + 0] = s;
        g_bnpart[((size_t)row * C + c) * 2 + 1] = q;
    }
}

// ------------------- K4: finalize BN stats -------------------
__global__ void k_stats()
{
    __shared__ float ss[256], sq[256];
    int t = threadIdx.x;           // 256
    int c = t & 63, qtr = t >> 6;
    float s = 0.f, q = 0.f;
    int r0 = qtr * 128;
    #pragma unroll 8
    for (int r = r0; r < r0 + 128; r++) {
        s += g_bnpart[((size_t)r * C + c) * 2 + 0];
        q += g_bnpart[((size_t)r * C + c) * 2 + 1];
    }
    ss[t] = s; sq[t] = q;
    __syncthreads();
    if (qtr == 0) {
        float S = ((ss[c] + ss[64 + c]) + (ss[128 + c] + ss[192 + c]));
        float Q = ((sq[c] + sq[64 + c]) + (sq[128 + c] + sq[192 + c]));
        float mean = S * (1.f / (float)BN_COUNT);
        float var  = Q * (1.f / (float)BN_COUNT) - mean * mean;
        g_bnstat[c * 2 + 0] = mean;
        g_bnstat[c * 2 + 1] = rsqrtf(var + 1e-5f);
    }
}

// ------------------- K5: normalize -------------------
__global__ void k_norm(const float* __restrict__ gamma, const float* __restrict__ beta,
                       float* __restrict__ out)
{
    size_t i4 = (size_t)blockIdx.x * 256 + threadIdx.x;
    int c = (int)((i4 >> 12) & 63);
    float mean = g_bnstat[c * 2 + 0];
    float rstd = g_bnstat[c * 2 + 1];
    float ga = gamma[c] * rstd;
    float be = beta[c] - mean * ga;
    float4 z = ((const float4*)g_z)[i4];
    float4 r;
    r.x = z.x * ga + be; r.y = z.y * ga + be;
    r.z = z.z * ga + be; r.w = z.w * ga + be;
    ((float4*)out)[i4] = r;
}

// ------------------------------- launch -------------------------------
extern "C" void kernel_launch(void* const* d_in, const int* in_sizes, int n_in,
                              void* d_out, int out_size)
{
    const float* x     = (const float*)d_in[0];
    const float* g_w   = (const float*)d_in[1];
    const float* g_b   = (const float*)d_in[2];
    const float* th_w  = (const float*)d_in[3];
    const float* th_b  = (const float*)d_in[4];
    const float* ph_w  = (const float*)d_in[5];
    const float* ph_b  = (const float*)d_in[6];
    const float* out_w = (const float*)d_in[7];
    const float* out_b = (const float*)d_in[8];
    const float* gamma = (const float*)d_in[9];
    const float* beta  = (const float*)d_in[10];
    float* out = (float*)d_out;

    k_down_proj<<<B * 64, 256>>>(x, g_w, g_b, th_w, th_b, ph_w, ph_b);
    k_attn<<<B * 32 * SPLITK, 128>>>();
    k_merge<<<64, 256>>>();
    k_out<<<B * H, 256>>>(x, out_w, out_b);
    k_stats<<<1, 256>>>();
    k_norm<<<4096, 256>>>(gamma, beta, out);
}